// round 2
// baseline (speedup 1.0000x reference)
#include <cuda_runtime.h>
#include <cuda_bf16.h>
#include <math_constants.h>

// Problem dims
#define BB 4
#define SS 4096
#define DD 768
#define RR (BB*SS)        // 16384 rows
#define FF 385            // rfft bins of 768
// Padded layout constants
#define TW_COLS 896       // 770 padded to 7*128
#define SLOT    772       // per-matrix column slot in Gt (770 padded to mult of 4)
#define GT_LD   2440      // 3*SLOT + (TW_COLS - SLOT) overwrite room; 1544+896=2440
#define XF_ROWS 2432      // 19*128 >= 2314 (max used col 1544+769)
#define IT_ROWS 784       // 770 padded to 49*16 (K of stage-4)

// ---------------- scratch (device globals; no allocation allowed) ----------------
__device__ float d_Tw  [DD * TW_COLS];        // DFT twiddles   [o=768, j=896]
__device__ float d_IT  [IT_ROWS * DD];        // inverse-DFT    [j2=784, d=768]
__device__ float d_Gt  [DD * GT_LD];          // folded weights [in=768, col=2440]
__device__ float d_Xt  [DD * RR];             // x transposed   [in=768, r=16384]
__device__ float d_XFt [XF_ROWS * RR];        // freq proj (T)  [col, r]
__device__ float d_OutFt[IT_ROWS * RR];       // mem*conj(q) (T)[j2,  r]

// ---------------- table init ----------------
__global__ void init_tables_kernel() {
    const int idx = blockIdx.x * blockDim.x + threadIdx.x;
    const float w = 2.0f * CUDART_PI_F / (float)DD;

    // Tw[o, j]: j<385 -> cos(2pi f o/768); 385<=j<770 -> -sin; else 0
    if (idx < DD * TW_COLS) {
        int o = idx / TW_COLS;
        int j = idx % TW_COLS;
        float v = 0.0f;
        if (j < 2 * FF) {
            int f = (j < FF) ? j : (j - FF);
            int r = (f * o) % DD;          // exact integer reduction
            float ang = w * (float)r;
            v = (j < FF) ? cosf(ang) : -sinf(ang);
        }
        d_Tw[idx] = v;
    }
    // IT[j2, d]
    if (idx < IT_ROWS * DD) {
        int j = idx / DD;
        int d = idx % DD;
        float v = 0.0f;
        if (j < 2 * FF) {
            int f = (j < FF) ? j : (j - FF);
            int r = (f * d) % DD;
            float ang = w * (float)r;
            bool edge = (f == 0) || (f == DD / 2);
            float c = edge ? (1.0f / DD) : (2.0f / DD);
            if (j < FF)      v = c * cosf(ang);
            else             v = edge ? 0.0f : -c * sinf(ang);
        }
        d_IT[idx] = v;
    }
    // zero the pad rows of OutFt (rows 770..783) so stage-4 K-pad contributes 0
    if (idx < (IT_ROWS - 2 * FF) * RR) {
        d_OutFt[2 * FF * RR + idx] = 0.0f;
    }
}

// ---------------- X transpose: [16384,768] -> [768,16384] ----------------
__global__ void transpose_x_kernel(const float* __restrict__ in) {
    __shared__ float tile[32][33];
    const int c0 = blockIdx.x * 32;   // col in X (feature)
    const int r0 = blockIdx.y * 32;   // row in X
    const int tx = threadIdx.x, ty = threadIdx.y;
#pragma unroll
    for (int i = 0; i < 32; i += 8)
        tile[ty + i][tx] = in[(r0 + ty + i) * DD + c0 + tx];
    __syncthreads();
#pragma unroll
    for (int i = 0; i < 32; i += 8)
        d_Xt[(c0 + ty + i) * RR + r0 + tx] = tile[tx][ty + i];
}

// ---------------- generic TN SGEMM: C[m,n] = sum_k A[k,m]*B[k,n] ----------------
// Requires: M%128==0, N%128==0, K%16==0, lda/ldb/ldc multiples of 4,
// and all base pointers 16B-aligned.
// MODE 0: C[m*ldc+n]=acc     MODE 1: C[n*ldc+m]=acc (transposed write)
// MODE 2: C[m*ldc+n]=xres[m*ldc+n] + gain[0]*acc
template <int MODE>
__global__ __launch_bounds__(256) void gemm_tn_kernel(
    int M, int N, int K,
    const float* __restrict__ A, int lda,
    const float* __restrict__ B, int ldb,
    float* __restrict__ C, int ldc,
    const float* __restrict__ xres, const float* __restrict__ gain)
{
    __shared__ __align__(16) float As[16][128];
    __shared__ __align__(16) float Bs[16][128];

    const int t  = threadIdx.x;          // 0..255
    const int tx = t & 15;               // n-tile lane
    const int ty = t >> 4;               // m-tile lane
    const int m0 = blockIdx.y * 128;
    const int n0 = blockIdx.x * 128;

    float acc[8][8];
#pragma unroll
    for (int i = 0; i < 8; i++)
#pragma unroll
        for (int j = 0; j < 8; j++) acc[i][j] = 0.0f;

    for (int k0 = 0; k0 < K; k0 += 16) {
        // cooperative loads: 512 float4 slots per matrix, 2 per thread
#pragma unroll
        for (int r = 0; r < 2; r++) {
            int s  = t + r * 256;
            int k  = s >> 5;             // 0..15
            int mq = s & 31;             // 0..31 -> 4 floats
            *(float4*)&As[k][mq * 4] =
                *(const float4*)&A[(size_t)(k0 + k) * lda + m0 + mq * 4];
            *(float4*)&Bs[k][mq * 4] =
                *(const float4*)&B[(size_t)(k0 + k) * ldb + n0 + mq * 4];
        }
        __syncthreads();

#pragma unroll
        for (int kk = 0; kk < 16; kk++) {
            float a[8], b[8];
            *(float4*)(a)     = *(float4*)&As[kk][ty * 8];
            *(float4*)(a + 4) = *(float4*)&As[kk][ty * 8 + 4];
            *(float4*)(b)     = *(float4*)&Bs[kk][tx * 8];
            *(float4*)(b + 4) = *(float4*)&Bs[kk][tx * 8 + 4];
#pragma unroll
            for (int i = 0; i < 8; i++)
#pragma unroll
                for (int j = 0; j < 8; j++)
                    acc[i][j] = fmaf(a[i], b[j], acc[i][j]);
        }
        __syncthreads();
    }

    if (MODE == 0) {
#pragma unroll
        for (int i = 0; i < 8; i++) {
            size_t row = (size_t)(m0 + ty * 8 + i) * ldc + n0 + tx * 8;
            *(float4*)&C[row]     = make_float4(acc[i][0], acc[i][1], acc[i][2], acc[i][3]);
            *(float4*)&C[row + 4] = make_float4(acc[i][4], acc[i][5], acc[i][6], acc[i][7]);
        }
    } else if (MODE == 1) {
#pragma unroll
        for (int j = 0; j < 8; j++) {
            size_t row = (size_t)(n0 + tx * 8 + j) * ldc + m0 + ty * 8;
            *(float4*)&C[row]     = make_float4(acc[0][j], acc[1][j], acc[2][j], acc[3][j]);
            *(float4*)&C[row + 4] = make_float4(acc[4][j], acc[5][j], acc[6][j], acc[7][j]);
        }
    } else {
        const float g = gain[0];
#pragma unroll
        for (int i = 0; i < 8; i++) {
            size_t row = (size_t)(m0 + ty * 8 + i) * ldc + n0 + tx * 8;
            float4 x0 = *(const float4*)&xres[row];
            float4 x1 = *(const float4*)&xres[row + 4];
            *(float4*)&C[row] = make_float4(x0.x + g * acc[i][0], x0.y + g * acc[i][1],
                                            x0.z + g * acc[i][2], x0.w + g * acc[i][3]);
            *(float4*)&C[row + 4] = make_float4(x1.x + g * acc[i][4], x1.y + g * acc[i][5],
                                                x1.z + g * acc[i][6], x1.w + g * acc[i][7]);
        }
    }
}

// ---------------- causal scan over S per (batch, frequency) ----------------
// XFt rows (ld = 16384), slot stride SLOT=772:
//   kre=f, kim=385+f, vre=772+f, vim=772+385+f, qre=1544+f, qim=1544+385+f
__global__ __launch_bounds__(512) void scan_kernel() {
    const int f = blockIdx.x;            // 0..384
    const int b = blockIdx.y;            // 0..3
    const int base = b * SS;
    const int t = threadIdx.x;           // 0..511, 8 elems each
    const int s0 = t * 8;

    const float* kre = d_XFt + (size_t)(0 * SLOT + f)      * RR + base;
    const float* kim = d_XFt + (size_t)(0 * SLOT + FF + f) * RR + base;
    const float* vre = d_XFt + (size_t)(1 * SLOT + f)      * RR + base;
    const float* vim = d_XFt + (size_t)(1 * SLOT + FF + f) * RR + base;
    const float* qre = d_XFt + (size_t)(2 * SLOT + f)      * RR + base;
    const float* qim = d_XFt + (size_t)(2 * SLOT + FF + f) * RR + base;

    float kr[8], ki[8], vr[8], vi[8], qr[8], qi[8];
#pragma unroll
    for (int h = 0; h < 2; h++) {
        *(float4*)(kr + 4 * h) = *(const float4*)(kre + s0 + 4 * h);
        *(float4*)(ki + 4 * h) = *(const float4*)(kim + s0 + 4 * h);
        *(float4*)(vr + 4 * h) = *(const float4*)(vre + s0 + 4 * h);
        *(float4*)(vi + 4 * h) = *(const float4*)(vim + s0 + 4 * h);
        *(float4*)(qr + 4 * h) = *(const float4*)(qre + s0 + 4 * h);
        *(float4*)(qi + 4 * h) = *(const float4*)(qim + s0 + 4 * h);
    }

    // local inclusive scan of z = kf*vf
    float lr[8], li[8];
    float runr = 0.0f, runi = 0.0f;
#pragma unroll
    for (int i = 0; i < 8; i++) {
        float zr = kr[i] * vr[i] - ki[i] * vi[i];
        float zi = kr[i] * vi[i] + ki[i] * vr[i];
        runr += zr; runi += zi;
        lr[i] = runr; li[i] = runi;
    }

    __shared__ float sr[512], si[512];
    sr[t] = runr; si[t] = runi;
    __syncthreads();
    for (int off = 1; off < 512; off <<= 1) {
        float ar = 0.0f, ai = 0.0f;
        if (t >= off) { ar = sr[t - off]; ai = si[t - off]; }
        __syncthreads();
        sr[t] += ar; si[t] += ai;
        __syncthreads();
    }
    const float exr = (t > 0) ? sr[t - 1] : 0.0f;
    const float exi = (t > 0) ? si[t - 1] : 0.0f;

    float* ore = d_OutFt + (size_t)(f) * RR + base;
    float* oim = d_OutFt + (size_t)(FF + f) * RR + base;
    float outr[8], outi[8];
#pragma unroll
    for (int i = 0; i < 8; i++) {
        float mr = exr + lr[i];
        float mi = exi + li[i];
        outr[i] = mr * qr[i] + mi * qi[i];   // Re(mem * conj(q))
        outi[i] = mi * qr[i] - mr * qi[i];   // Im(mem * conj(q))
    }
#pragma unroll
    for (int h = 0; h < 2; h++) {
        *(float4*)(ore + s0 + 4 * h) = *(float4*)(outr + 4 * h);
        *(float4*)(oim + s0 + 4 * h) = *(float4*)(outi + 4 * h);
    }
}

// ---------------- launch ----------------
extern "C" void kernel_launch(void* const* d_in, const int* in_sizes, int n_in,
                              void* d_out, int out_size) {
    const float* x    = (const float*)d_in[0];
    const float* Wk   = (const float*)d_in[1];
    const float* Wv   = (const float*)d_in[2];
    const float* Wq   = (const float*)d_in[3];
    const float* gain = (const float*)d_in[4];
    float* out = (float*)d_out;

    float *pTw, *pIT, *pGt, *pXt, *pXFt, *pOutFt;
    cudaGetSymbolAddress((void**)&pTw,   d_Tw);
    cudaGetSymbolAddress((void**)&pIT,   d_IT);
    cudaGetSymbolAddress((void**)&pGt,   d_Gt);
    cudaGetSymbolAddress((void**)&pXt,   d_Xt);
    cudaGetSymbolAddress((void**)&pXFt,  d_XFt);
    cudaGetSymbolAddress((void**)&pOutFt,d_OutFt);

    // 0) tables (twiddles, inverse-DFT, pad-row zeroing)
    {
        int total = DD * TW_COLS;               // 688128 (largest)
        init_tables_kernel<<<(total + 255) / 256, 256>>>();
    }

    // 1) transpose x -> Xt [768, 16384]
    transpose_x_kernel<<<dim3(DD / 32, RR / 32), dim3(32, 8)>>>(x);

    // 2) fold DFT into weights: Gt[in, slot*m + j] = sum_o W[o,in] * Tw[o,j]
    //    M=768 (in), N=896 (j, padded), K=768 (o). Sequential launches: later
    //    matrices overwrite the previous one's zero-padded overflow columns.
    //    Slot offsets 0/772/1544 are multiples of 4 -> float4 stores aligned.
    {
        dim3 grid(TW_COLS / 128, DD / 128);
        gemm_tn_kernel<0><<<grid, 256>>>(DD, TW_COLS, DD, Wk, DD, pTw, TW_COLS,
                                         pGt + 0 * SLOT, GT_LD, nullptr, nullptr);
        gemm_tn_kernel<0><<<grid, 256>>>(DD, TW_COLS, DD, Wv, DD, pTw, TW_COLS,
                                         pGt + 1 * SLOT, GT_LD, nullptr, nullptr);
        gemm_tn_kernel<0><<<grid, 256>>>(DD, TW_COLS, DD, Wq, DD, pTw, TW_COLS,
                                         pGt + 2 * SLOT, GT_LD, nullptr, nullptr);
    }

    // 3) big projection GEMM, transposed output: XFt[col, r] = sum_in Xt[in,r]*Gt[in,col]
    {
        dim3 grid(XF_ROWS / 128, RR / 128);
        gemm_tn_kernel<1><<<grid, 256>>>(RR, XF_ROWS, DD, pXt, RR, pGt, GT_LD,
                                         pXFt, RR, nullptr, nullptr);
    }

    // 4) causal complex scan per (b, f)
    scan_kernel<<<dim3(FF, BB), 512>>>();

    // 5) inverse DFT GEMM + residual epilogue:
    //    out[r,d] = x[r,d] + gain * sum_j2 OutFt[j2,r] * IT[j2,d]
    {
        dim3 grid(DD / 128, RR / 128);
        gemm_tn_kernel<2><<<grid, 256>>>(RR, DD, IT_ROWS, pOutFt, RR, pIT, DD,
                                         out, DD, x, gain);
    }
}

// round 4
// speedup vs baseline: 2.3377x; 2.3377x over previous
#include <cuda_runtime.h>
#include <cuda_bf16.h>
#include <math_constants.h>
#include <cstdint>

// Problem dims
#define BB 4
#define SS 4096
#define DD 768
#define RR (BB*SS)        // 16384
#define FF 385            // rfft bins
// Layouts
#define TW_COLS 896       // 770 padded
#define SLOT    772       // per-matrix col slot in G'
#define GP_ROWS 2440
#define MROWS   2432      // stage-3 M total (19*128)
#define K3      2304      // 3*768  (split-stacked K, stage-3)
#define SEG5    832       // 770 padded to 13*64
#define K5      2496      // 3*832  (split-stacked K, stage-5)
#define OFLD    784       // OutF fp32 ld (interleaved re/im cols 0..769)

// ---------------- scratch ----------------
__device__ float          d_Tw  [DD * TW_COLS];
__device__ float          d_Gp  [GP_ROWS * DD];          // G'[col, in] fp32
__device__ __nv_bfloat16  d_Gs  [MROWS * K3];            // A stage-3 (hi,lo,hi)
__device__ __nv_bfloat16  d_Xs  [(size_t)RR * K3];       // B stage-3 (hi,hi,lo)
__device__ float          d_XFt [(size_t)MROWS * RR];    // [col, r] fp32
__device__ float          d_OutF[(size_t)RR * OFLD];     // [r, 2f interleaved]
__device__ __nv_bfloat16  d_OFs [(size_t)RR * K5];       // A stage-5 (hi,lo,hi)
__device__ __nv_bfloat16  d_ITb [DD * K5];               // B stage-5 (hi,hi,lo)

// ---------------- helpers ----------------
__device__ __forceinline__ uint32_t s2u(const void* p) {
    uint32_t a;
    asm("{ .reg .u64 t; cvta.to.shared.u64 t, %1; cvt.u32.u64 %0, t; }" : "=r"(a) : "l"(p));
    return a;
}
__device__ __forceinline__ uint32_t swz(uint32_t o) { return o ^ ((o >> 3) & 0x70); }
#define CP16(dst, src) asm volatile("cp.async.cg.shared.global [%0], [%1], 16;" :: "r"(dst), "l"(src))
#define CP_COMMIT()    asm volatile("cp.async.commit_group;" ::: "memory")

__device__ __forceinline__ void split2(float v, __nv_bfloat16& h, __nv_bfloat16& l) {
    h = __float2bfloat16(v);
    l = __float2bfloat16(v - __bfloat162float(h));
}
__device__ __forceinline__ uint32_t packbf(__nv_bfloat16 a, __nv_bfloat16 b) {
    return (uint32_t)__bfloat16_as_ushort(a) | ((uint32_t)__bfloat16_as_ushort(b) << 16);
}

// ---------------- init: Tw (fp32) + ITb (bf16 split, stage-5 B) ----------------
__global__ void init_tables_kernel() {
    const int idx = blockIdx.x * blockDim.x + threadIdx.x;
    const float w = 2.0f * CUDART_PI_F / (float)DD;

    if (idx < DD * TW_COLS) {
        int o = idx / TW_COLS;
        int j = idx % TW_COLS;
        float v = 0.0f;
        if (j < 2 * FF) {
            int f = (j < FF) ? j : (j - FF);
            int r = (f * o) % DD;
            float ang = w * (float)r;
            v = (j < FF) ? cosf(ang) : -sinf(ang);
        }
        d_Tw[idx] = v;
    }
    // ITb[d, seg*832 + j]: j=2f -> c*cos, j=2f+1 -> -c*sin (edge -> 0)
    if (idx < DD * SEG5) {
        int d = idx / SEG5;
        int j = idx % SEG5;
        float v = 0.0f;
        if (j < 2 * FF) {
            int f = j >> 1;
            bool edge = (f == 0) || (f == DD / 2);
            float c = edge ? (1.0f / DD) : (2.0f / DD);
            int r = (f * d) % DD;
            float ang = w * (float)r;
            if ((j & 1) == 0) v = c * cosf(ang);
            else              v = edge ? 0.0f : -c * sinf(ang);
        }
        __nv_bfloat16 h, l; split2(v, h, l);
        __nv_bfloat16* row = d_ITb + (size_t)d * K5;
        row[j] = h; row[SEG5 + j] = h; row[2 * SEG5 + j] = l;   // (hi, hi, lo)
    }
}

// ---------------- stage-2 fold (SIMT fp32, batched z=3, masked stores) ----------------
__global__ __launch_bounds__(256) void fold_kernel(
    const float* __restrict__ Wk, const float* __restrict__ Wv, const float* __restrict__ Wq)
{
    __shared__ __align__(16) float As[16][128];
    __shared__ __align__(16) float Bs[16][128];
    const float* A = (blockIdx.z == 0) ? Wk : (blockIdx.z == 1) ? Wv : Wq;
    float* C = d_Gp + (size_t)(blockIdx.z * SLOT) * DD;

    const int t = threadIdx.x;
    const int tx = t & 15, ty = t >> 4;
    const int m0 = blockIdx.y * 128;   // in
    const int n0 = blockIdx.x * 128;   // col within 896 window

    float acc[8][8];
#pragma unroll
    for (int i = 0; i < 8; i++)
#pragma unroll
        for (int j = 0; j < 8; j++) acc[i][j] = 0.0f;

    for (int k0 = 0; k0 < DD; k0 += 16) {
#pragma unroll
        for (int r = 0; r < 2; r++) {
            int s = t + r * 256;
            int k = s >> 5, mq = s & 31;
            *(float4*)&As[k][mq * 4] = *(const float4*)&A[(size_t)(k0 + k) * DD + m0 + mq * 4];
            *(float4*)&Bs[k][mq * 4] = *(const float4*)&d_Tw[(size_t)(k0 + k) * TW_COLS + n0 + mq * 4];
        }
        __syncthreads();
#pragma unroll
        for (int kk = 0; kk < 16; kk++) {
            float a[8], b[8];
            *(float4*)(a) = *(float4*)&As[kk][ty * 8]; *(float4*)(a + 4) = *(float4*)&As[kk][ty * 8 + 4];
            *(float4*)(b) = *(float4*)&Bs[kk][tx * 8]; *(float4*)(b + 4) = *(float4*)&Bs[kk][tx * 8 + 4];
#pragma unroll
            for (int i = 0; i < 8; i++)
#pragma unroll
                for (int j = 0; j < 8; j++) acc[i][j] = fmaf(a[i], b[j], acc[i][j]);
        }
        __syncthreads();
    }
    // transposed masked write: only cols < SLOT (each z owns rows z*SLOT + [0,772))
#pragma unroll
    for (int j = 0; j < 8; j++) {
        int col = n0 + tx * 8 + j;
        if (col < SLOT) {
            size_t row = (size_t)col * DD + m0 + ty * 8;
            *(float4*)&C[row]     = make_float4(acc[0][j], acc[1][j], acc[2][j], acc[3][j]);
            *(float4*)&C[row + 4] = make_float4(acc[4][j], acc[5][j], acc[6][j], acc[7][j]);
        }
    }
}

// ---------------- split kernels (vectorized, bf16x2 stores) ----------------
__global__ void split_G_kernel() {
    int idx = blockIdx.x * blockDim.x + threadIdx.x;
    if (idx >= MROWS * DD / 2) return;
    int row = idx / (DD / 2), cp = idx % (DD / 2);
    float2 v = *(const float2*)&d_Gp[(size_t)row * DD + cp * 2];
    __nv_bfloat16 h0, l0, h1, l1; split2(v.x, h0, l0); split2(v.y, h1, l1);
    uint32_t hp = packbf(h0, h1), lp = packbf(l0, l1);
    uint32_t* o = (uint32_t*)(d_Gs + (size_t)row * K3);
    o[cp] = hp; o[DD / 2 + cp] = lp; o[DD + cp] = hp;          // (hi, lo, hi)
}
__global__ void split_X_kernel(const float* __restrict__ x) {
    int idx = blockIdx.x * blockDim.x + threadIdx.x;
    if (idx >= RR * DD / 2) return;
    int r = idx / (DD / 2), cp = idx % (DD / 2);
    float2 v = *(const float2*)&x[(size_t)r * DD + cp * 2];
    __nv_bfloat16 h0, l0, h1, l1; split2(v.x, h0, l0); split2(v.y, h1, l1);
    uint32_t hp = packbf(h0, h1), lp = packbf(l0, l1);
    uint32_t* o = (uint32_t*)(d_Xs + (size_t)r * K3);
    o[cp] = hp; o[DD / 2 + cp] = hp; o[DD + cp] = lp;          // (hi, hi, lo)
}
__global__ void split_OF_kernel() {
    int idx = blockIdx.x * blockDim.x + threadIdx.x;
    if (idx >= RR * (SEG5 / 2)) return;
    int r = idx / (SEG5 / 2), jp = idx % (SEG5 / 2);
    float2 v = make_float2(0.0f, 0.0f);
    if (jp < FF) v = *(const float2*)&d_OutF[(size_t)r * OFLD + jp * 2];
    __nv_bfloat16 h0, l0, h1, l1; split2(v.x, h0, l0); split2(v.y, h1, l1);
    uint32_t hp = packbf(h0, h1), lp = packbf(l0, l1);
    uint32_t* o = (uint32_t*)(d_OFs + (size_t)r * K5);
    o[jp] = hp; o[SEG5 / 2 + jp] = lp; o[SEG5 + jp] = hp;      // (hi, lo, hi)
}

// ---------------- HMMA bf16 GEMM: C[m,n] = sum_k A[m,k]*B[n,k] ----------------
// 128x128 tile, 8 warps (2x4), 64x32 per warp, BK=64, double-buffered cp.async.
#define GEMM_SMEM (65536 + 1024)
template <int RESID>
__global__ __launch_bounds__(256) void hmma_gemm(
    int NKT,
    const __nv_bfloat16* __restrict__ A, int lda,
    const __nv_bfloat16* __restrict__ B, int ldb,
    float* __restrict__ C, int ldc,
    const float* __restrict__ resid, const float* __restrict__ gain)
{
    extern __shared__ char smraw[];
    const uint32_t sbase = (s2u(smraw) + 1023u) & ~1023u;
    const int t = threadIdx.x;
    const int lane = t & 31, w = t >> 5;
    const int wm = w >> 2, wn = w & 3;          // 2 x 4 warp grid
    const int m0 = blockIdx.x * 128, n0 = blockIdx.y * 128;

    float acc[4][4][4];
#pragma unroll
    for (int i = 0; i < 4; i++)
#pragma unroll
        for (int j = 0; j < 4; j++)
#pragma unroll
            for (int q = 0; q < 4; q++) acc[i][j][q] = 0.0f;

    // ldmatrix per-lane geometry
    const int arow = wm * 64 + (lane & 15);
    const int akoff = (lane >> 4) * 16;
    const int brow = wn * 32 + (lane & 7) + ((lane >> 4) * 8);
    const int bkoff = ((lane >> 3) & 1) * 16;

    auto issue = [&](int kt) {
        const uint32_t sA = sbase + (uint32_t)(kt & 1) * 32768u;
        const uint32_t sB = sA + 16384u;
#pragma unroll
        for (int i = 0; i < 4; i++) {
            const int s = t + i * 256;
            const int row = s >> 3, c16 = s & 7;
            const char* ga = (const char*)A + ((size_t)(m0 + row) * lda + kt * 64 + c16 * 8) * 2;
            CP16(sA + swz((uint32_t)(row * 128 + c16 * 16)), ga);
            const char* gb = (const char*)B + ((size_t)(n0 + row) * ldb + kt * 64 + c16 * 8) * 2;
            CP16(sB + swz((uint32_t)(row * 128 + c16 * 16)), gb);
        }
        CP_COMMIT();
    };

    issue(0);
    for (int kt = 0; kt < NKT; kt++) {
        if (kt + 1 < NKT) {
            issue(kt + 1);
            asm volatile("cp.async.wait_group 1;" ::: "memory");
        } else {
            asm volatile("cp.async.wait_group 0;" ::: "memory");
        }
        __syncthreads();
        const uint32_t sA = sbase + (uint32_t)(kt & 1) * 32768u;
        const uint32_t sB = sA + 16384u;
#pragma unroll
        for (int k16 = 0; k16 < 4; k16++) {
            uint32_t a[4][4];
#pragma unroll
            for (int mf = 0; mf < 4; mf++) {
                uint32_t addr = sA + swz((uint32_t)((arow + mf * 16) * 128 + k16 * 32 + akoff));
                asm volatile("ldmatrix.sync.aligned.m8n8.x4.shared.b16 {%0,%1,%2,%3}, [%4];"
                    : "=r"(a[mf][0]), "=r"(a[mf][1]), "=r"(a[mf][2]), "=r"(a[mf][3]) : "r"(addr));
            }
            uint32_t bfr[4][2];
#pragma unroll
            for (int p = 0; p < 2; p++) {
                uint32_t addr = sB + swz((uint32_t)((brow + p * 16) * 128 + k16 * 32 + bkoff));
                uint32_t q0, q1, q2, q3;
                asm volatile("ldmatrix.sync.aligned.m8n8.x4.shared.b16 {%0,%1,%2,%3}, [%4];"
                    : "=r"(q0), "=r"(q1), "=r"(q2), "=r"(q3) : "r"(addr));
                bfr[2 * p][0] = q0; bfr[2 * p][1] = q1;
                bfr[2 * p + 1][0] = q2; bfr[2 * p + 1][1] = q3;
            }
#pragma unroll
            for (int mf = 0; mf < 4; mf++)
#pragma unroll
                for (int nf = 0; nf < 4; nf++)
                    asm volatile(
                        "mma.sync.aligned.m16n8k16.row.col.f32.bf16.bf16.f32 "
                        "{%0,%1,%2,%3}, {%4,%5,%6,%7}, {%8,%9}, {%0,%1,%2,%3};"
                        : "+f"(acc[mf][nf][0]), "+f"(acc[mf][nf][1]),
                          "+f"(acc[mf][nf][2]), "+f"(acc[mf][nf][3])
                        : "r"(a[mf][0]), "r"(a[mf][1]), "r"(a[mf][2]), "r"(a[mf][3]),
                          "r"(bfr[nf][0]), "r"(bfr[nf][1]));
        }
        __syncthreads();
    }

    // epilogue
    const float g = RESID ? gain[0] : 0.0f;
    const int r = lane >> 2, c2 = (lane & 3) * 2;
#pragma unroll
    for (int mf = 0; mf < 4; mf++) {
#pragma unroll
        for (int nf = 0; nf < 4; nf++) {
            const int m = m0 + wm * 64 + mf * 16 + r;
            const int n = n0 + wn * 32 + nf * 8 + c2;
            const size_t o0 = (size_t)m * ldc + n;
            const size_t o1 = (size_t)(m + 8) * ldc + n;
            if (RESID) {
                float2 x0 = *(const float2*)&resid[o0];
                float2 x1 = *(const float2*)&resid[o1];
                *(float2*)&C[o0] = make_float2(x0.x + g * acc[mf][nf][0], x0.y + g * acc[mf][nf][1]);
                *(float2*)&C[o1] = make_float2(x1.x + g * acc[mf][nf][2], x1.y + g * acc[mf][nf][3]);
            } else {
                *(float2*)&C[o0] = make_float2(acc[mf][nf][0], acc[mf][nf][1]);
                *(float2*)&C[o1] = make_float2(acc[mf][nf][2], acc[mf][nf][3]);
            }
        }
    }
}

// ---------------- causal scan over S per (batch, frequency) ----------------
__global__ __launch_bounds__(512) void scan_kernel() {
    const int f = blockIdx.x;
    const int b = blockIdx.y;
    const int base = b * SS;
    const int t = threadIdx.x;
    const int s0 = t * 8;

    const float* kre = d_XFt + (size_t)(0 * SLOT + f)      * RR + base;
    const float* kim = d_XFt + (size_t)(0 * SLOT + FF + f) * RR + base;
    const float* vre = d_XFt + (size_t)(1 * SLOT + f)      * RR + base;
    const float* vim = d_XFt + (size_t)(1 * SLOT + FF + f) * RR + base;
    const float* qre = d_XFt + (size_t)(2 * SLOT + f)      * RR + base;
    const float* qim = d_XFt + (size_t)(2 * SLOT + FF + f) * RR + base;

    float kr[8], ki[8], vr[8], vi[8], qr[8], qi[8];
#pragma unroll
    for (int h = 0; h < 2; h++) {
        *(float4*)(kr + 4 * h) = *(const float4*)(kre + s0 + 4 * h);
        *(float4*)(ki + 4 * h) = *(const float4*)(kim + s0 + 4 * h);
        *(float4*)(vr + 4 * h) = *(const float4*)(vre + s0 + 4 * h);
        *(float4*)(vi + 4 * h) = *(const float4*)(vim + s0 + 4 * h);
        *(float4*)(qr + 4 * h) = *(const float4*)(qre + s0 + 4 * h);
        *(float4*)(qi + 4 * h) = *(const float4*)(qim + s0 + 4 * h);
    }

    float lr[8], li[8], runr = 0.0f, runi = 0.0f;
#pragma unroll
    for (int i = 0; i < 8; i++) {
        float zr = kr[i] * vr[i] - ki[i] * vi[i];
        float zi = kr[i] * vi[i] + ki[i] * vr[i];
        runr += zr; runi += zi;
        lr[i] = runr; li[i] = runi;
    }

    __shared__ float sr[512], si[512];
    sr[t] = runr; si[t] = runi;
    __syncthreads();
    for (int off = 1; off < 512; off <<= 1) {
        float ar = 0.0f, ai = 0.0f;
        if (t >= off) { ar = sr[t - off]; ai = si[t - off]; }
        __syncthreads();
        sr[t] += ar; si[t] += ai;
        __syncthreads();
    }
    const float exr = (t > 0) ? sr[t - 1] : 0.0f;
    const float exi = (t > 0) ? si[t - 1] : 0.0f;

#pragma unroll
    for (int i = 0; i < 8; i++) {
        float mr = exr + lr[i];
        float mi = exi + li[i];
        float2 o;
        o.x = mr * qr[i] + mi * qi[i];   // Re(mem*conj(q))
        o.y = mi * qr[i] - mr * qi[i];   // Im
        *(float2*)&d_OutF[(size_t)(base + s0 + i) * OFLD + 2 * f] = o;
    }
}

// ---------------- launch ----------------
extern "C" void kernel_launch(void* const* d_in, const int* in_sizes, int n_in,
                              void* d_out, int out_size) {
    const float* x    = (const float*)d_in[0];
    const float* Wk   = (const float*)d_in[1];
    const float* Wv   = (const float*)d_in[2];
    const float* Wq   = (const float*)d_in[3];
    const float* gain = (const float*)d_in[4];
    float* out = (float*)d_out;

    __nv_bfloat16 *pGs, *pXs, *pOFs, *pITb;
    float *pXFt;
    cudaGetSymbolAddress((void**)&pGs,  d_Gs);
    cudaGetSymbolAddress((void**)&pXs,  d_Xs);
    cudaGetSymbolAddress((void**)&pOFs, d_OFs);
    cudaGetSymbolAddress((void**)&pITb, d_ITb);
    cudaGetSymbolAddress((void**)&pXFt, d_XFt);

    cudaFuncSetAttribute(hmma_gemm<0>, cudaFuncAttributeMaxDynamicSharedMemorySize, GEMM_SMEM);
    cudaFuncSetAttribute(hmma_gemm<1>, cudaFuncAttributeMaxDynamicSharedMemorySize, GEMM_SMEM);

    // 0) tables
    init_tables_kernel<<<(DD * TW_COLS + 255) / 256, 256>>>();

    // 1) fold DFT into weights (batched k,v,q): G'[col,in]
    fold_kernel<<<dim3(TW_COLS / 128, DD / 128, 3), 256>>>(Wk, Wv, Wq);

    // 2) split operands to stacked bf16
    split_G_kernel<<<(MROWS * DD / 2 + 255) / 256, 256>>>();
    split_X_kernel<<<(RR * DD / 2 + 255) / 256, 256>>>(x);

    // 3) stage-3 tensor GEMM: XFt[col, r]  (M=2432, N=16384, K=2304)
    hmma_gemm<0><<<dim3(MROWS / 128, RR / 128), 256, GEMM_SMEM>>>(
        K3 / 64, pGs, K3, pXs, K3, pXFt, RR, nullptr, nullptr);

    // 4) causal scan -> OutF[r, 2f interleaved]
    scan_kernel<<<dim3(FF, BB), 512>>>();

    // 5) split OutF
    split_OF_kernel<<<(RR * (SEG5 / 2) + 255) / 256, 256>>>();

    // 6) stage-5 tensor GEMM + residual: out[r,d]  (M=16384, N=768, K=2496)
    hmma_gemm<1><<<dim3(RR / 128, DD / 128), 256, GEMM_SMEM>>>(
        K5 / 64, pOFs, K5, pITb, K5, out, DD, x, gain);
}

// round 5
// speedup vs baseline: 2.5991x; 1.1119x over previous
#include <cuda_runtime.h>
#include <cuda_bf16.h>
#include <math_constants.h>
#include <cstdint>

// Problem dims
#define BB 4
#define SS 4096
#define DD 768
#define RR (BB*SS)        // 16384
#define FF 385            // rfft bins
// Layouts
#define SLOT    772       // per-matrix col slot in Gs
#define MROWS   2432      // stage-3 M (19*128)
#define GS_ROWS 2440
#define K3      2304      // 3*768
#define SEG5    832       // 770 -> 13*64
#define K5      2496      // 3*832
#define TWROWS  896       // fold M (7*128)

// ---------------- scratch ----------------
__device__ __nv_bfloat16 d_TwS[TWROWS * K3];             // Tw^T split (hi,lo,hi)  [col, o-k]
__device__ __nv_bfloat16 d_Ws [3 * DD * K3];             // W^T split (hi,hi,lo)   [z][in, o-k]
__device__ __nv_bfloat16 d_Gs [GS_ROWS * K3];            // folded A (hi,lo,hi)    [col, in-k]
__device__ __nv_bfloat16 d_Xs [(size_t)RR * K3];         // B stage-3 (hi,hi,lo)   [r, in-k]
__device__ float         d_XFt[(size_t)MROWS * RR];      // [col, r] fp32
__device__ __nv_bfloat16 d_OFs[(size_t)RR * K5];         // A stage-5 (hi,lo,hi)   [r, j-k]
__device__ __nv_bfloat16 d_ITb[DD * K5];                 // B stage-5 (hi,hi,lo)   [d, j-k]

// ---------------- helpers ----------------
__device__ __forceinline__ uint32_t s2u(const void* p) {
    uint32_t a;
    asm("{ .reg .u64 t; cvta.to.shared.u64 t, %1; cvt.u32.u64 %0, t; }" : "=r"(a) : "l"(p));
    return a;
}
__device__ __forceinline__ uint32_t swz(uint32_t o) { return o ^ ((o >> 3) & 0x70); }
#define CP16(dst, src) asm volatile("cp.async.cg.shared.global [%0], [%1], 16;" :: "r"(dst), "l"(src))
#define CP_COMMIT()    asm volatile("cp.async.commit_group;" ::: "memory")

__device__ __forceinline__ void split2(float v, __nv_bfloat16& h, __nv_bfloat16& l) {
    h = __float2bfloat16(v);
    l = __float2bfloat16(v - __bfloat162float(h));
}
__device__ __forceinline__ uint32_t packbf(__nv_bfloat16 a, __nv_bfloat16 b) {
    return (uint32_t)__bfloat16_as_ushort(a) | ((uint32_t)__bfloat16_as_ushort(b) << 16);
}
__device__ __forceinline__ uint32_t packsplit(float v0, float v1, uint32_t& lo) {
    __nv_bfloat16 h0, l0, h1, l1; split2(v0, h0, l0); split2(v1, h1, l1);
    lo = packbf(l0, l1);
    return packbf(h0, h1);
}

// ---------------- init: TwS (A of fold) + ITb (B of stage-5) ----------------
__global__ void init_tables_kernel() {
    const int idx = blockIdx.x * blockDim.x + threadIdx.x;
    const float w = 2.0f * CUDART_PI_F / (float)DD;

    // TwS[c, o] = Tw[o, c]; c<385: cos, 385<=c<770: -sin, else 0. Pairs over o.
    if (idx < TWROWS * (DD / 2)) {
        int c = idx / (DD / 2), op = idx % (DD / 2);
        float v0 = 0.0f, v1 = 0.0f;
        if (c < 2 * FF) {
            int f = (c < FF) ? c : (c - FF);
            int r0 = (f * (2 * op)) % DD, r1 = (f * (2 * op + 1)) % DD;
            if (c < FF) { v0 = cosf(w * (float)r0);  v1 = cosf(w * (float)r1); }
            else        { v0 = -sinf(w * (float)r0); v1 = -sinf(w * (float)r1); }
        }
        uint32_t lp, hp = packsplit(v0, v1, lp);
        uint32_t* row = (uint32_t*)(d_TwS + (size_t)c * K3);
        row[op] = hp; row[DD / 2 + op] = lp; row[DD + op] = hp;     // (hi, lo, hi)
    }
    // ITb[d, j]: j=2f -> c*cos, j=2f+1 -> -c*sin (edge f=0 or 384 -> sin term 0)
    if (idx < DD * (SEG5 / 2)) {
        int d = idx / (SEG5 / 2), fp = idx % (SEG5 / 2);
        float v0 = 0.0f, v1 = 0.0f;
        if (fp < FF) {
            int f = fp;
            bool edge = (f == 0) || (f == DD / 2);
            float c = edge ? (1.0f / DD) : (2.0f / DD);
            int r = (f * d) % DD;
            float ang = w * (float)r;
            v0 = c * cosf(ang);
            v1 = edge ? 0.0f : -c * sinf(ang);
        }
        uint32_t lp, hp = packsplit(v0, v1, lp);
        uint32_t* row = (uint32_t*)(d_ITb + (size_t)d * K5);
        row[fp] = hp; row[SEG5 / 2 + fp] = hp; row[SEG5 + fp] = lp; // (hi, hi, lo)
    }
}

// ---------------- W^T split: Ws[z][in, o] = split(W_z[o, in]) ----------------
__global__ void splitW_kernel(const float* __restrict__ Wk, const float* __restrict__ Wv,
                              const float* __restrict__ Wq) {
    int idx = blockIdx.x * blockDim.x + threadIdx.x;
    if (idx >= 3 * (DD / 2) * DD) return;
    int z = idx / ((DD / 2) * DD);
    int rem = idx % ((DD / 2) * DD);
    int op = rem / DD, in = rem % DD;          // in fastest -> coalesced loads
    const float* W = (z == 0) ? Wk : (z == 1) ? Wv : Wq;
    float v0 = W[(size_t)(2 * op) * DD + in];
    float v1 = W[(size_t)(2 * op + 1) * DD + in];
    uint32_t lp, hp = packsplit(v0, v1, lp);
    uint32_t* row = (uint32_t*)(d_Ws + (size_t)(z * DD + in) * K3);
    row[op] = hp; row[DD / 2 + op] = hp; row[DD + op] = lp;         // (hi, hi, lo)
}

// ---------------- X split ----------------
__global__ void split_X_kernel(const float* __restrict__ x) {
    int idx = blockIdx.x * blockDim.x + threadIdx.x;
    if (idx >= RR * DD / 2) return;
    int r = idx / (DD / 2), cp = idx % (DD / 2);
    float2 v = *(const float2*)&x[(size_t)r * DD + cp * 2];
    uint32_t lp, hp = packsplit(v.x, v.y, lp);
    uint32_t* o = (uint32_t*)(d_Xs + (size_t)r * K3);
    o[cp] = hp; o[DD / 2 + cp] = hp; o[DD + cp] = lp;               // (hi, hi, lo)
}

// ---------------- HMMA bf16 GEMM: C[m,n] = sum_k A[m,k]*B[n,k] ----------------
// CTA tile 128x256, 8 warps (2m x 4n), warp tile 64x64, BK=64, double-buffered.
// MODE 0: fp32 C.  MODE 1: C = resid + gain*acc.  MODE 2 (fold): bf16-split store
//         into d_Gs (+ blockIdx.z slot), masked to local col < SLOT.
#define GEMM_SMEM (2 * 49152 + 1024)
template <int MODE>
__global__ __launch_bounds__(256, 1) void hmma_gemm(
    int NKT,
    const __nv_bfloat16* __restrict__ A, int lda,
    const __nv_bfloat16* __restrict__ B, int ldb,
    float* __restrict__ C, int ldc,
    const float* __restrict__ resid, const float* __restrict__ gain)
{
    extern __shared__ char smraw[];
    const uint32_t sbase = (s2u(smraw) + 1023u) & ~1023u;
    const int t = threadIdx.x;
    const int lane = t & 31, w = t >> 5;
    const int wm = w >> 2, wn = w & 3;           // 2 x 4 warps
    const int m0 = blockIdx.x * 128, n0 = blockIdx.y * 256;
    if (MODE == 2) B += (size_t)blockIdx.z * DD * ldb;

    float acc[4][8][4];
#pragma unroll
    for (int i = 0; i < 4; i++)
#pragma unroll
        for (int j = 0; j < 8; j++)
#pragma unroll
            for (int q = 0; q < 4; q++) acc[i][j][q] = 0.0f;

    const int arow = wm * 64 + (lane & 15);
    const int akoff = (lane >> 4) * 16;
    const int brow0 = (lane & 7) + ((lane >> 4) * 8);
    const int bkoff = ((lane >> 3) & 1) * 16;

    auto issue = [&](int kt) {
        const uint32_t sA = sbase + (uint32_t)(kt & 1) * 49152u;
        const uint32_t sB = sA + 16384u;
#pragma unroll
        for (int i = 0; i < 4; i++) {
            const int s = t + i * 256, row = s >> 3, c = s & 7;
            CP16(sA + swz((uint32_t)(row * 128 + c * 16)),
                 (const char*)A + ((size_t)(m0 + row) * lda + kt * 64 + c * 8) * 2);
        }
#pragma unroll
        for (int i = 0; i < 8; i++) {
            const int s = t + i * 256, row = s >> 3, c = s & 7;
            CP16(sB + swz((uint32_t)(row * 128 + c * 16)),
                 (const char*)B + ((size_t)(n0 + row) * ldb + kt * 64 + c * 8) * 2);
        }
        CP_COMMIT();
    };

    issue(0);
    for (int kt = 0; kt < NKT; kt++) {
        if (kt + 1 < NKT) {
            issue(kt + 1);
            asm volatile("cp.async.wait_group 1;" ::: "memory");
        } else {
            asm volatile("cp.async.wait_group 0;" ::: "memory");
        }
        __syncthreads();
        const uint32_t sA = sbase + (uint32_t)(kt & 1) * 49152u;
        const uint32_t sB = sA + 16384u;
#pragma unroll
        for (int k16 = 0; k16 < 4; k16++) {
            uint32_t a[4][4];
#pragma unroll
            for (int mf = 0; mf < 4; mf++) {
                uint32_t addr = sA + swz((uint32_t)((arow + mf * 16) * 128 + k16 * 32 + akoff));
                asm volatile("ldmatrix.sync.aligned.m8n8.x4.shared.b16 {%0,%1,%2,%3}, [%4];"
                    : "=r"(a[mf][0]), "=r"(a[mf][1]), "=r"(a[mf][2]), "=r"(a[mf][3]) : "r"(addr));
            }
#pragma unroll
            for (int p = 0; p < 4; p++) {
                uint32_t q0, q1, q2, q3;
                uint32_t addr = sB + swz((uint32_t)((wn * 64 + p * 16 + brow0) * 128 + k16 * 32 + bkoff));
                asm volatile("ldmatrix.sync.aligned.m8n8.x4.shared.b16 {%0,%1,%2,%3}, [%4];"
                    : "=r"(q0), "=r"(q1), "=r"(q2), "=r"(q3) : "r"(addr));
#pragma unroll
                for (int mf = 0; mf < 4; mf++) {
                    asm volatile(
                        "mma.sync.aligned.m16n8k16.row.col.f32.bf16.bf16.f32 "
                        "{%0,%1,%2,%3}, {%4,%5,%6,%7}, {%8,%9}, {%0,%1,%2,%3};"
                        : "+f"(acc[mf][2 * p][0]), "+f"(acc[mf][2 * p][1]),
                          "+f"(acc[mf][2 * p][2]), "+f"(acc[mf][2 * p][3])
                        : "r"(a[mf][0]), "r"(a[mf][1]), "r"(a[mf][2]), "r"(a[mf][3]),
                          "r"(q0), "r"(q1));
                    asm volatile(
                        "mma.sync.aligned.m16n8k16.row.col.f32.bf16.bf16.f32 "
                        "{%0,%1,%2,%3}, {%4,%5,%6,%7}, {%8,%9}, {%0,%1,%2,%3};"
                        : "+f"(acc[mf][2 * p + 1][0]), "+f"(acc[mf][2 * p + 1][1]),
                          "+f"(acc[mf][2 * p + 1][2]), "+f"(acc[mf][2 * p + 1][3])
                        : "r"(a[mf][0]), "r"(a[mf][1]), "r"(a[mf][2]), "r"(a[mf][3]),
                          "r"(q2), "r"(q3));
                }
            }
        }
        __syncthreads();
    }

    // ---------------- epilogue ----------------
    const int r = lane >> 2, c2 = (lane & 3) * 2;
    if (MODE == 2) {
        __nv_bfloat16* gbase = d_Gs + (size_t)blockIdx.z * SLOT * K3;
#pragma unroll
        for (int mf = 0; mf < 4; mf++) {
#pragma unroll
            for (int nf = 0; nf < 8; nf++) {
                const int ml = m0 + wm * 64 + mf * 16 + r;      // local col in 896-window
                const int n = n0 + wn * 64 + nf * 8 + c2;       // in (0..767)
#pragma unroll
                for (int hh = 0; hh < 2; hh++) {
                    const int mrow = ml + hh * 8;
                    if (mrow < SLOT) {
                        uint32_t lp, hp = packsplit(acc[mf][nf][2 * hh], acc[mf][nf][2 * hh + 1], lp);
                        uint32_t* orow = (uint32_t*)(gbase + (size_t)mrow * K3);
                        orow[n / 2] = hp; orow[DD / 2 + n / 2] = lp; orow[DD + n / 2] = hp;
                    }
                }
            }
        }
        return;
    }
    const float g = (MODE == 1) ? gain[0] : 0.0f;
#pragma unroll
    for (int mf = 0; mf < 4; mf++) {
#pragma unroll
        for (int nf = 0; nf < 8; nf++) {
            const int m = m0 + wm * 64 + mf * 16 + r;
            const int n = n0 + wn * 64 + nf * 8 + c2;
            const size_t o0 = (size_t)m * ldc + n;
            const size_t o1 = (size_t)(m + 8) * ldc + n;
            if (MODE == 1) {
                float2 x0 = *(const float2*)&resid[o0];
                float2 x1 = *(const float2*)&resid[o1];
                *(float2*)&C[o0] = make_float2(x0.x + g * acc[mf][nf][0], x0.y + g * acc[mf][nf][1]);
                *(float2*)&C[o1] = make_float2(x1.x + g * acc[mf][nf][2], x1.y + g * acc[mf][nf][3]);
            } else {
                *(float2*)&C[o0] = make_float2(acc[mf][nf][0], acc[mf][nf][1]);
                *(float2*)&C[o1] = make_float2(acc[mf][nf][2], acc[mf][nf][3]);
            }
        }
    }
}

// ---------------- causal scan, fused bf16-split output ----------------
// XFt rows (ld = RR), slot stride SLOT.
__global__ __launch_bounds__(512) void scan_kernel() {
    const int f = blockIdx.x;
    const int b = blockIdx.y;
    const int base = b * SS;
    const int t = threadIdx.x;
    const int s0 = t * 8;

    const float* kre = d_XFt + (size_t)(0 * SLOT + f)      * RR + base;
    const float* kim = d_XFt + (size_t)(0 * SLOT + FF + f) * RR + base;
    const float* vre = d_XFt + (size_t)(1 * SLOT + f)      * RR + base;
    const float* vim = d_XFt + (size_t)(1 * SLOT + FF + f) * RR + base;
    const float* qre = d_XFt + (size_t)(2 * SLOT + f)      * RR + base;
    const float* qim = d_XFt + (size_t)(2 * SLOT + FF + f) * RR + base;

    float kr[8], ki[8], vr[8], vi[8], qr[8], qi[8];
#pragma unroll
    for (int h = 0; h < 2; h++) {
        *(float4*)(kr + 4 * h) = *(const float4*)(kre + s0 + 4 * h);
        *(float4*)(ki + 4 * h) = *(const float4*)(kim + s0 + 4 * h);
        *(float4*)(vr + 4 * h) = *(const float4*)(vre + s0 + 4 * h);
        *(float4*)(vi + 4 * h) = *(const float4*)(vim + s0 + 4 * h);
        *(float4*)(qr + 4 * h) = *(const float4*)(qre + s0 + 4 * h);
        *(float4*)(qi + 4 * h) = *(const float4*)(qim + s0 + 4 * h);
    }

    float lr[8], li[8], runr = 0.0f, runi = 0.0f;
#pragma unroll
    for (int i = 0; i < 8; i++) {
        float zr = kr[i] * vr[i] - ki[i] * vi[i];
        float zi = kr[i] * vi[i] + ki[i] * vr[i];
        runr += zr; runi += zi;
        lr[i] = runr; li[i] = runi;
    }

    __shared__ float sr[512], si[512];
    sr[t] = runr; si[t] = runi;
    __syncthreads();
    for (int off = 1; off < 512; off <<= 1) {
        float ar = 0.0f, ai = 0.0f;
        if (t >= off) { ar = sr[t - off]; ai = si[t - off]; }
        __syncthreads();
        sr[t] += ar; si[t] += ai;
        __syncthreads();
    }
    const float exr = (t > 0) ? sr[t - 1] : 0.0f;
    const float exi = (t > 0) ? si[t - 1] : 0.0f;

#pragma unroll
    for (int i = 0; i < 8; i++) {
        float mr = exr + lr[i];
        float mi = exi + li[i];
        float ox = mr * qr[i] + mi * qi[i];   // Re(mem*conj(q)) -> j=2f
        float oy = mi * qr[i] - mr * qi[i];   // Im              -> j=2f+1
        uint32_t lp, hp = packsplit(ox, oy, lp);
        uint32_t* orow = (uint32_t*)(d_OFs + (size_t)(base + s0 + i) * K5);
        orow[f] = hp; orow[SEG5 / 2 + f] = lp; orow[SEG5 + f] = hp;   // (hi, lo, hi)
    }
}

// ---------------- launch ----------------
extern "C" void kernel_launch(void* const* d_in, const int* in_sizes, int n_in,
                              void* d_out, int out_size) {
    const float* x    = (const float*)d_in[0];
    const float* Wk   = (const float*)d_in[1];
    const float* Wv   = (const float*)d_in[2];
    const float* Wq   = (const float*)d_in[3];
    const float* gain = (const float*)d_in[4];
    float* out = (float*)d_out;

    __nv_bfloat16 *pTwS, *pWs, *pGs, *pXs, *pOFs, *pITb;
    float *pXFt;
    cudaGetSymbolAddress((void**)&pTwS, d_TwS);
    cudaGetSymbolAddress((void**)&pWs,  d_Ws);
    cudaGetSymbolAddress((void**)&pGs,  d_Gs);
    cudaGetSymbolAddress((void**)&pXs,  d_Xs);
    cudaGetSymbolAddress((void**)&pOFs, d_OFs);
    cudaGetSymbolAddress((void**)&pITb, d_ITb);
    cudaGetSymbolAddress((void**)&pXFt, d_XFt);

    cudaFuncSetAttribute(hmma_gemm<0>, cudaFuncAttributeMaxDynamicSharedMemorySize, GEMM_SMEM);
    cudaFuncSetAttribute(hmma_gemm<1>, cudaFuncAttributeMaxDynamicSharedMemorySize, GEMM_SMEM);
    cudaFuncSetAttribute(hmma_gemm<2>, cudaFuncAttributeMaxDynamicSharedMemorySize, GEMM_SMEM);

    // 0) tables: TwS (fold A) + ITb (stage-5 B)
    init_tables_kernel<<<(DD * (SEG5 / 2) + 255) / 256, 256>>>();

    // 1) W^T split (fold B) + X split (stage-3 B)
    splitW_kernel<<<(3 * (DD / 2) * DD + 255) / 256, 256>>>(Wk, Wv, Wq);
    split_X_kernel<<<(RR * DD / 2 + 255) / 256, 256>>>(x);

    // 2) fold GEMM (HMMA, all 3 weights concurrent, masked split-store into Gs)
    hmma_gemm<2><<<dim3(TWROWS / 128, DD / 256, 3), 256, GEMM_SMEM>>>(
        K3 / 64, pTwS, K3, pWs, K3, nullptr, 0, nullptr, nullptr);

    // 3) stage-3 GEMM: XFt[col, r]  (M=2432, N=16384, K=2304)
    hmma_gemm<0><<<dim3(MROWS / 128, RR / 256), 256, GEMM_SMEM>>>(
        K3 / 64, pGs, K3, pXs, K3, pXFt, RR, nullptr, nullptr);

    // 4) causal scan -> OFs (bf16 split, fused)
    scan_kernel<<<dim3(FF, BB), 512>>>();

    // 5) stage-5 GEMM + residual: out[r,d]  (M=16384, N=768, K=2496)
    hmma_gemm<1><<<dim3(RR / 128, DD / 256), 256, GEMM_SMEM>>>(
        K5 / 64, pOFs, K5, pITb, K5, out, DD, x, gain);
}

// round 7
// speedup vs baseline: 3.5652x; 1.3717x over previous
#include <cuda_runtime.h>
#include <cuda_bf16.h>
#include <cuda_fp16.h>
#include <math_constants.h>
#include <cstdint>

// Problem dims
#define BB 4
#define SS 4096
#define DD 768
#define RR (BB*SS)        // 16384
#define FF 385            // rfft bins
// Layouts
#define SLOT    772       // per-matrix col slot in Gs
#define MROWS   2432      // stage-3 M (19*128)
#define GS_ROWS 2440
#define K3      2304      // fold K (bf16 3-term)
#define KA3     1536      // stage-3 A row len (fp16 hi|lo)
#define KB3     768       // stage-3 B row len (fp16 hi)
#define KA5     1664      // stage-5 A row len (fp16 hi|lo), 2*832
#define KB5     832       // stage-5 B row len (fp16 hi), 770 padded
#define TWROWS  896       // fold M (7*128)
#define SCALE5  (1.0f/4096.0f)
#define ISCALE5 4096.0f

// ---------------- scratch ----------------
__device__ __nv_bfloat16 d_TwS[TWROWS * K3];             // fold A: Tw^T (hi,lo,hi) bf16
__device__ __nv_bfloat16 d_Ws [3 * DD * K3];             // fold B: W^T (hi,hi,lo) bf16
__device__ __half        d_Gs [GS_ROWS * KA3];           // stage-3 A: folded G (hi|lo) fp16
__device__ __half        d_Xs [(size_t)RR * KB3];        // stage-3 B: x (hi) fp16
__device__ float         d_XFt[(size_t)MROWS * RR];      // [col, r] fp32
__device__ __half        d_OFs[(size_t)RR * KA5];        // stage-5 A: scaled memq (hi|lo) fp16
__device__ __half        d_ITb[DD * KB5];                // stage-5 B: inv-DFT (hi) fp16

// ---------------- helpers ----------------
__device__ __forceinline__ uint32_t s2u(const void* p) {
    uint32_t a;
    asm("{ .reg .u64 t; cvta.to.shared.u64 t, %1; cvt.u32.u64 %0, t; }" : "=r"(a) : "l"(p));
    return a;
}
__device__ __forceinline__ uint32_t swz(uint32_t o) { return o ^ ((o >> 3) & 0x70); }
#define CP16(dst, src) asm volatile("cp.async.cg.shared.global [%0], [%1], 16;" :: "r"(dst), "l"(src))
#define CP_COMMIT()    asm volatile("cp.async.commit_group;" ::: "memory")

__device__ __forceinline__ uint32_t packh(__half a, __half b) {
    return (uint32_t)__half_as_ushort(a) | ((uint32_t)__half_as_ushort(b) << 16);
}
__device__ __forceinline__ uint32_t packsplit_h(float v0, float v1, uint32_t& lo) {
    __half h0 = __float2half(v0); __half l0 = __float2half(v0 - __half2float(h0));
    __half h1 = __float2half(v1); __half l1 = __float2half(v1 - __half2float(h1));
    lo = packh(l0, l1);
    return packh(h0, h1);
}
__device__ __forceinline__ void split2b(float v, __nv_bfloat16& h, __nv_bfloat16& l) {
    h = __float2bfloat16(v);
    l = __float2bfloat16(v - __bfloat162float(h));
}
__device__ __forceinline__ uint32_t packbf(__nv_bfloat16 a, __nv_bfloat16 b) {
    return (uint32_t)__bfloat16_as_ushort(a) | ((uint32_t)__bfloat16_as_ushort(b) << 16);
}
__device__ __forceinline__ uint32_t packsplit_b(float v0, float v1, uint32_t& lo) {
    __nv_bfloat16 h0, l0, h1, l1; split2b(v0, h0, l0); split2b(v1, h1, l1);
    lo = packbf(l0, l1);
    return packbf(h0, h1);
}

template <bool BF>
__device__ __forceinline__ void mma16816(float* d, const uint32_t* a, uint32_t b0, uint32_t b1) {
    if constexpr (BF)
        asm volatile(
            "mma.sync.aligned.m16n8k16.row.col.f32.bf16.bf16.f32 "
            "{%0,%1,%2,%3}, {%4,%5,%6,%7}, {%8,%9}, {%0,%1,%2,%3};"
            : "+f"(d[0]), "+f"(d[1]), "+f"(d[2]), "+f"(d[3])
            : "r"(a[0]), "r"(a[1]), "r"(a[2]), "r"(a[3]), "r"(b0), "r"(b1));
    else
        asm volatile(
            "mma.sync.aligned.m16n8k16.row.col.f32.f16.f16.f32 "
            "{%0,%1,%2,%3}, {%4,%5,%6,%7}, {%8,%9}, {%0,%1,%2,%3};"
            : "+f"(d[0]), "+f"(d[1]), "+f"(d[2]), "+f"(d[3])
            : "r"(a[0]), "r"(a[1]), "r"(a[2]), "r"(a[3]), "r"(b0), "r"(b1));
}

// ---------------- init: TwS (fold A, bf16 3-term) + ITb (stage-5 B, fp16 hi) ----------------
__global__ void init_tables_kernel() {
    const int idx = blockIdx.x * blockDim.x + threadIdx.x;
    const float w = 2.0f * CUDART_PI_F / (float)DD;

    if (idx < TWROWS * (DD / 2)) {
        int c = idx / (DD / 2), op = idx % (DD / 2);
        float v0 = 0.0f, v1 = 0.0f;
        if (c < 2 * FF) {
            int f = (c < FF) ? c : (c - FF);
            int r0 = (f * (2 * op)) % DD, r1 = (f * (2 * op + 1)) % DD;
            if (c < FF) { v0 = cosf(w * (float)r0);  v1 = cosf(w * (float)r1); }
            else        { v0 = -sinf(w * (float)r0); v1 = -sinf(w * (float)r1); }
        }
        uint32_t lp, hp = packsplit_b(v0, v1, lp);
        uint32_t* row = (uint32_t*)(d_TwS + (size_t)c * K3);
        row[op] = hp; row[DD / 2 + op] = lp; row[DD + op] = hp;     // (hi, lo, hi)
    }
    // ITb[d, j]: j=2f -> c*cos, j=2f+1 -> -c*sin (edge f=0/384 -> sin term 0); fp16 hi
    if (idx < DD * (KB5 / 2)) {
        int d = idx / (KB5 / 2), fp = idx % (KB5 / 2);
        float v0 = 0.0f, v1 = 0.0f;
        if (fp < FF) {
            int f = fp;
            bool edge = (f == 0) || (f == DD / 2);
            float c = edge ? (1.0f / DD) : (2.0f / DD);
            int r = (f * d) % DD;
            float ang = w * (float)r;
            v0 = c * cosf(ang);
            v1 = edge ? 0.0f : -c * sinf(ang);
        }
        uint32_t* row = (uint32_t*)(d_ITb + (size_t)d * KB5);
        row[fp] = packh(__float2half(v0), __float2half(v1));
    }
}

// ---------------- W^T split (fold B, bf16 3-term) ----------------
__global__ void splitW_kernel(const float* __restrict__ Wk, const float* __restrict__ Wv,
                              const float* __restrict__ Wq) {
    int idx = blockIdx.x * blockDim.x + threadIdx.x;
    if (idx >= 3 * (DD / 2) * DD) return;
    int z = idx / ((DD / 2) * DD);
    int rem = idx % ((DD / 2) * DD);
    int op = rem / DD, in = rem % DD;
    const float* W = (z == 0) ? Wk : (z == 1) ? Wv : Wq;
    float v0 = W[(size_t)(2 * op) * DD + in];
    float v1 = W[(size_t)(2 * op + 1) * DD + in];
    uint32_t lp, hp = packsplit_b(v0, v1, lp);
    uint32_t* row = (uint32_t*)(d_Ws + (size_t)(z * DD + in) * K3);
    row[op] = hp; row[DD / 2 + op] = hp; row[DD + op] = lp;         // (hi, hi, lo)
}

// ---------------- X convert (stage-3 B, fp16 hi only) ----------------
__global__ void split_X_kernel(const float* __restrict__ x) {
    int idx = blockIdx.x * blockDim.x + threadIdx.x;
    if (idx >= RR * DD / 2) return;
    int r = idx / (DD / 2), cp = idx % (DD / 2);
    float2 v = *(const float2*)&x[(size_t)r * DD + cp * 2];
    ((uint32_t*)(d_Xs + (size_t)r * KB3))[cp] = packh(__float2half(v.x), __float2half(v.y));
}

// ---------------- HMMA GEMM: C[m,n] = sum_k A[m,k]*B[n,k] ----------------
// CTA tile 128x256, 8 warps (2m x 4n), warp tile 64x64, BK=64, double-buffered.
// B chunk index wraps at BPER (hi-block reuse for the fp16 2-term split).
// MODE 0: fp32 C.  MODE 1: C = resid + gain[0]*4096*acc.
// MODE 2 (fold, bf16): fp16-split store into d_Gs (+z slot), masked col<SLOT.
#define GEMM_SMEM (2 * 49152 + 1024)
template <int MODE>
__global__ __launch_bounds__(256, 1) void hmma_gemm(
    int NKT, int BPER,
    const __nv_bfloat16* __restrict__ A, int lda,
    const __nv_bfloat16* __restrict__ B, int ldb,
    float* __restrict__ C, int ldc,
    const float* __restrict__ resid, const float* __restrict__ gain)
{
    extern __shared__ char smraw[];
    const uint32_t sbase = (s2u(smraw) + 1023u) & ~1023u;
    const int t = threadIdx.x;
    const int lane = t & 31, w = t >> 5;
    const int wm = w >> 2, wn = w & 3;
    const int m0 = blockIdx.x * 128, n0 = blockIdx.y * 256;
    if (MODE == 2) B += (size_t)blockIdx.z * DD * ldb;

    float acc[4][8][4];
#pragma unroll
    for (int i = 0; i < 4; i++)
#pragma unroll
        for (int j = 0; j < 8; j++)
#pragma unroll
            for (int q = 0; q < 4; q++) acc[i][j][q] = 0.0f;

    const int arow = wm * 64 + (lane & 15);
    const int akoff = (lane >> 4) * 16;
    const int brow0 = (lane & 7) + ((lane >> 4) * 8);
    const int bkoff = ((lane >> 3) & 1) * 16;

    auto issue = [&](int kt) {
        const uint32_t sA = sbase + (uint32_t)(kt & 1) * 49152u;
        const uint32_t sB = sA + 16384u;
        const int bkt = kt % BPER;
#pragma unroll
        for (int i = 0; i < 4; i++) {
            const int s = t + i * 256, row = s >> 3, c = s & 7;
            CP16(sA + swz((uint32_t)(row * 128 + c * 16)),
                 (const char*)A + ((size_t)(m0 + row) * lda + kt * 64 + c * 8) * 2);
        }
#pragma unroll
        for (int i = 0; i < 8; i++) {
            const int s = t + i * 256, row = s >> 3, c = s & 7;
            CP16(sB + swz((uint32_t)(row * 128 + c * 16)),
                 (const char*)B + ((size_t)(n0 + row) * ldb + bkt * 64 + c * 8) * 2);
        }
        CP_COMMIT();
    };

    issue(0);
    for (int kt = 0; kt < NKT; kt++) {
        if (kt + 1 < NKT) {
            issue(kt + 1);
            asm volatile("cp.async.wait_group 1;" ::: "memory");
        } else {
            asm volatile("cp.async.wait_group 0;" ::: "memory");
        }
        __syncthreads();
        const uint32_t sA = sbase + (uint32_t)(kt & 1) * 49152u;
        const uint32_t sB = sA + 16384u;
#pragma unroll
        for (int k16 = 0; k16 < 4; k16++) {
            uint32_t a[4][4];
#pragma unroll
            for (int mf = 0; mf < 4; mf++) {
                uint32_t addr = sA + swz((uint32_t)((arow + mf * 16) * 128 + k16 * 32 + akoff));
                asm volatile("ldmatrix.sync.aligned.m8n8.x4.shared.b16 {%0,%1,%2,%3}, [%4];"
                    : "=r"(a[mf][0]), "=r"(a[mf][1]), "=r"(a[mf][2]), "=r"(a[mf][3]) : "r"(addr));
            }
#pragma unroll
            for (int p = 0; p < 4; p++) {
                uint32_t q0, q1, q2, q3;
                uint32_t addr = sB + swz((uint32_t)((wn * 64 + p * 16 + brow0) * 128 + k16 * 32 + bkoff));
                asm volatile("ldmatrix.sync.aligned.m8n8.x4.shared.b16 {%0,%1,%2,%3}, [%4];"
                    : "=r"(q0), "=r"(q1), "=r"(q2), "=r"(q3) : "r"(addr));
#pragma unroll
                for (int mf = 0; mf < 4; mf++) {
                    mma16816<MODE == 2>(acc[mf][2 * p], a[mf], q0, q1);
                    mma16816<MODE == 2>(acc[mf][2 * p + 1], a[mf], q2, q3);
                }
            }
        }
        __syncthreads();
    }

    // ---------------- epilogue ----------------
    const int r = lane >> 2, c2 = (lane & 3) * 2;
    if (MODE == 2) {
        __half* gbase = d_Gs + (size_t)blockIdx.z * SLOT * KA3;
#pragma unroll
        for (int mf = 0; mf < 4; mf++) {
#pragma unroll
            for (int nf = 0; nf < 8; nf++) {
                const int ml = m0 + wm * 64 + mf * 16 + r;
                const int n = n0 + wn * 64 + nf * 8 + c2;
#pragma unroll
                for (int hh = 0; hh < 2; hh++) {
                    const int mrow = ml + hh * 8;
                    if (mrow < SLOT) {
                        uint32_t lp, hp = packsplit_h(acc[mf][nf][2 * hh], acc[mf][nf][2 * hh + 1], lp);
                        uint32_t* orow = (uint32_t*)(gbase + (size_t)mrow * KA3);
                        orow[n / 2] = hp; orow[KB3 / 2 + n / 2] = lp;   // (hi | lo)
                    }
                }
            }
        }
        return;
    }
    const float g = (MODE == 1) ? gain[0] * ISCALE5 : 0.0f;
#pragma unroll
    for (int mf = 0; mf < 4; mf++) {
#pragma unroll
        for (int nf = 0; nf < 8; nf++) {
            const int m = m0 + wm * 64 + mf * 16 + r;
            const int n = n0 + wn * 64 + nf * 8 + c2;
            const size_t o0 = (size_t)m * ldc + n;
            const size_t o1 = (size_t)(m + 8) * ldc + n;
            if (MODE == 1) {
                float2 x0 = *(const float2*)&resid[o0];
                float2 x1 = *(const float2*)&resid[o1];
                *(float2*)&C[o0] = make_float2(x0.x + g * acc[mf][nf][0], x0.y + g * acc[mf][nf][1]);
                *(float2*)&C[o1] = make_float2(x1.x + g * acc[mf][nf][2], x1.y + g * acc[mf][nf][3]);
            } else {
                *(float2*)&C[o0] = make_float2(acc[mf][nf][0], acc[mf][nf][1]);
                *(float2*)&C[o1] = make_float2(acc[mf][nf][2], acc[mf][nf][3]);
            }
        }
    }
}

// ---------------- causal scan, fused fp16-split + 2^-12 prescale ----------------
__global__ __launch_bounds__(512) void scan_kernel() {
    const int f = blockIdx.x;
    const int b = blockIdx.y;
    const int base = b * SS;
    const int t = threadIdx.x;
    const int s0 = t * 8;

    const float* kre = d_XFt + (size_t)(0 * SLOT + f)      * RR + base;
    const float* kim = d_XFt + (size_t)(0 * SLOT + FF + f) * RR + base;
    const float* vre = d_XFt + (size_t)(1 * SLOT + f)      * RR + base;
    const float* vim = d_XFt + (size_t)(1 * SLOT + FF + f) * RR + base;
    const float* qre = d_XFt + (size_t)(2 * SLOT + f)      * RR + base;
    const float* qim = d_XFt + (size_t)(2 * SLOT + FF + f) * RR + base;

    float kr[8], ki[8], vr[8], vi[8], qr[8], qi[8];
#pragma unroll
    for (int h = 0; h < 2; h++) {
        *(float4*)(kr + 4 * h) = *(const float4*)(kre + s0 + 4 * h);
        *(float4*)(ki + 4 * h) = *(const float4*)(kim + s0 + 4 * h);
        *(float4*)(vr + 4 * h) = *(const float4*)(vre + s0 + 4 * h);
        *(float4*)(vi + 4 * h) = *(const float4*)(vim + s0 + 4 * h);
        *(float4*)(qr + 4 * h) = *(const float4*)(qre + s0 + 4 * h);
        *(float4*)(qi + 4 * h) = *(const float4*)(qim + s0 + 4 * h);
    }

    float lr[8], li[8], runr = 0.0f, runi = 0.0f;
#pragma unroll
    for (int i = 0; i < 8; i++) {
        float zr = kr[i] * vr[i] - ki[i] * vi[i];
        float zi = kr[i] * vi[i] + ki[i] * vr[i];
        runr += zr; runi += zi;
        lr[i] = runr; li[i] = runi;
    }

    __shared__ float sr[512], si[512];
    sr[t] = runr; si[t] = runi;
    __syncthreads();
    for (int off = 1; off < 512; off <<= 1) {
        float ar = 0.0f, ai = 0.0f;
        if (t >= off) { ar = sr[t - off]; ai = si[t - off]; }
        __syncthreads();
        sr[t] += ar; si[t] += ai;
        __syncthreads();
    }
    const float exr = (t > 0) ? sr[t - 1] : 0.0f;
    const float exi = (t > 0) ? si[t - 1] : 0.0f;

#pragma unroll
    for (int i = 0; i < 8; i++) {
        float mr = exr + lr[i];
        float mi = exi + li[i];
        float ox = (mr * qr[i] + mi * qi[i]) * SCALE5;   // Re -> j=2f
        float oy = (mi * qr[i] - mr * qi[i]) * SCALE5;   // Im -> j=2f+1
        uint32_t lp, hp = packsplit_h(ox, oy, lp);
        uint32_t* orow = (uint32_t*)(d_OFs + (size_t)(base + s0 + i) * KA5);
        orow[f] = hp; orow[KB5 / 2 + f] = lp;            // (hi | lo)
    }
}

// ---------------- launch ----------------
extern "C" void kernel_launch(void* const* d_in, const int* in_sizes, int n_in,
                              void* d_out, int out_size) {
    const float* x    = (const float*)d_in[0];
    const float* Wk   = (const float*)d_in[1];
    const float* Wv   = (const float*)d_in[2];
    const float* Wq   = (const float*)d_in[3];
    const float* gain = (const float*)d_in[4];
    float* out = (float*)d_out;

    void *pTwS, *pWs, *pGs, *pXs, *pOFs, *pITb, *pXFt;
    cudaGetSymbolAddress(&pTwS, d_TwS);
    cudaGetSymbolAddress(&pWs,  d_Ws);
    cudaGetSymbolAddress(&pGs,  d_Gs);
    cudaGetSymbolAddress(&pXs,  d_Xs);
    cudaGetSymbolAddress(&pOFs, d_OFs);
    cudaGetSymbolAddress(&pITb, d_ITb);
    cudaGetSymbolAddress(&pXFt, d_XFt);

    cudaFuncSetAttribute(hmma_gemm<0>, cudaFuncAttributeMaxDynamicSharedMemorySize, GEMM_SMEM);
    cudaFuncSetAttribute(hmma_gemm<1>, cudaFuncAttributeMaxDynamicSharedMemorySize, GEMM_SMEM);
    cudaFuncSetAttribute(hmma_gemm<2>, cudaFuncAttributeMaxDynamicSharedMemorySize, GEMM_SMEM);

    // 0) tables
    init_tables_kernel<<<(TWROWS * (DD / 2) + 255) / 256, 256>>>();

    // 1) W^T split (fold B) + X fp16 convert (stage-3 B)
    splitW_kernel<<<(3 * (DD / 2) * DD + 255) / 256, 256>>>(Wk, Wv, Wq);
    split_X_kernel<<<(RR * DD / 2 + 255) / 256, 256>>>(x);

    // 2) fold GEMM (bf16 3-term, 3 weights concurrent, fp16-split store into Gs)
    hmma_gemm<2><<<dim3(TWROWS / 128, DD / 256, 3), 256, GEMM_SMEM>>>(
        K3 / 64, K3 / 64,
        (const __nv_bfloat16*)pTwS, K3, (const __nv_bfloat16*)pWs, K3,
        nullptr, 0, nullptr, nullptr);

    // 3) stage-3 GEMM (fp16 2-term): XFt[col, r]  M=2432, N=16384, K=1536 (B period 768)
    hmma_gemm<0><<<dim3(MROWS / 128, RR / 256), 256, GEMM_SMEM>>>(
        KA3 / 64, KB3 / 64,
        (const __nv_bfloat16*)pGs, KA3, (const __nv_bfloat16*)pXs, KB3,
        (float*)pXFt, RR, nullptr, nullptr);

    // 4) causal scan -> OFs (fp16 split + prescale, fused)
    scan_kernel<<<dim3(FF, BB), 512>>>();

    // 5) stage-5 GEMM + residual (fp16 2-term): out[r,d]  M=16384, N=768, K=1664 (B period 832)
    hmma_gemm<1><<<dim3(RR / 128, DD / 256), 256, GEMM_SMEM>>>(
        KA5 / 64, KB5 / 64,
        (const __nv_bfloat16*)pOFs, KA5, (const __nv_bfloat16*)pITb, KB5,
        out, DD, x, gain);
}

// round 8
// speedup vs baseline: 3.7468x; 1.0509x over previous
#include <cuda_runtime.h>
#include <cuda_bf16.h>
#include <cuda_fp16.h>
#include <math_constants.h>
#include <cstdint>

// Problem dims
#define BB 4
#define SS 4096
#define DD 768
#define RR (BB*SS)        // 16384
#define FF 385            // rfft bins
// Layouts
#define SLOT    772
#define MROWS   2432
#define GS_ROWS 2440
#define K3      2304      // fold K (bf16 3-term)
#define KA3     1536      // stage-3 A row len (fp16 hi|lo)
#define KB3     768       // stage-3 B row len (fp16 hi)
#define KA5     1664      // stage-5 A row len (fp16 hi|lo)
#define KB5     832       // stage-5 B row len (fp16 hi)
#define TWROWS  896
#define SCALE5  (1.0f/4096.0f)
#define ISCALE5 4096.0f

// ---------------- scratch ----------------
__device__ __nv_bfloat16 d_TwS[TWROWS * K3];
__device__ __nv_bfloat16 d_Ws [3 * DD * K3];
__device__ __half        d_Gs [GS_ROWS * KA3];
__device__ __half        d_Xs [(size_t)RR * KB3];
__device__ float         d_XFt[(size_t)MROWS * RR];
__device__ __half        d_OFs[(size_t)RR * KA5];
__device__ __half        d_ITb[DD * KB5];

// ---------------- helpers ----------------
__device__ __forceinline__ uint32_t s2u(const void* p) {
    uint32_t a;
    asm("{ .reg .u64 t; cvta.to.shared.u64 t, %1; cvt.u32.u64 %0, t; }" : "=r"(a) : "l"(p));
    return a;
}
__device__ __forceinline__ uint32_t swz(uint32_t o) { return o ^ ((o >> 3) & 0x70); }
#define CP16(dst, src) asm volatile("cp.async.cg.shared.global [%0], [%1], 16;" :: "r"(dst), "l"(src))
#define CP_COMMIT()    asm volatile("cp.async.commit_group;" ::: "memory")

__device__ __forceinline__ uint32_t packh(__half a, __half b) {
    return (uint32_t)__half_as_ushort(a) | ((uint32_t)__half_as_ushort(b) << 16);
}
__device__ __forceinline__ uint32_t packsplit_h(float v0, float v1, uint32_t& lo) {
    __half h0 = __float2half(v0); __half l0 = __float2half(v0 - __half2float(h0));
    __half h1 = __float2half(v1); __half l1 = __float2half(v1 - __half2float(h1));
    lo = packh(l0, l1);
    return packh(h0, h1);
}
__device__ __forceinline__ void split2b(float v, __nv_bfloat16& h, __nv_bfloat16& l) {
    h = __float2bfloat16(v);
    l = __float2bfloat16(v - __bfloat162float(h));
}
__device__ __forceinline__ uint32_t packbf(__nv_bfloat16 a, __nv_bfloat16 b) {
    return (uint32_t)__bfloat16_as_ushort(a) | ((uint32_t)__bfloat16_as_ushort(b) << 16);
}
__device__ __forceinline__ uint32_t packsplit_b(float v0, float v1, uint32_t& lo) {
    __nv_bfloat16 h0, l0, h1, l1; split2b(v0, h0, l0); split2b(v1, h1, l1);
    lo = packbf(l0, l1);
    return packbf(h0, h1);
}

template <bool BF>
__device__ __forceinline__ void mma16816(float* d, const uint32_t* a, uint32_t b0, uint32_t b1) {
    if constexpr (BF)
        asm volatile(
            "mma.sync.aligned.m16n8k16.row.col.f32.bf16.bf16.f32 "
            "{%0,%1,%2,%3}, {%4,%5,%6,%7}, {%8,%9}, {%0,%1,%2,%3};"
            : "+f"(d[0]), "+f"(d[1]), "+f"(d[2]), "+f"(d[3])
            : "r"(a[0]), "r"(a[1]), "r"(a[2]), "r"(a[3]), "r"(b0), "r"(b1));
    else
        asm volatile(
            "mma.sync.aligned.m16n8k16.row.col.f32.f16.f16.f32 "
            "{%0,%1,%2,%3}, {%4,%5,%6,%7}, {%8,%9}, {%0,%1,%2,%3};"
            : "+f"(d[0]), "+f"(d[1]), "+f"(d[2]), "+f"(d[3])
            : "r"(a[0]), "r"(a[1]), "r"(a[2]), "r"(a[3]), "r"(b0), "r"(b1));
}

// ---------------- init: TwS + ITb ----------------
__global__ void init_tables_kernel() {
    const int idx = blockIdx.x * blockDim.x + threadIdx.x;
    const float w = 2.0f * CUDART_PI_F / (float)DD;

    if (idx < TWROWS * (DD / 2)) {
        int c = idx / (DD / 2), op = idx % (DD / 2);
        float v0 = 0.0f, v1 = 0.0f;
        if (c < 2 * FF) {
            int f = (c < FF) ? c : (c - FF);
            int r0 = (f * (2 * op)) % DD, r1 = (f * (2 * op + 1)) % DD;
            if (c < FF) { v0 = cosf(w * (float)r0);  v1 = cosf(w * (float)r1); }
            else        { v0 = -sinf(w * (float)r0); v1 = -sinf(w * (float)r1); }
        }
        uint32_t lp, hp = packsplit_b(v0, v1, lp);
        uint32_t* row = (uint32_t*)(d_TwS + (size_t)c * K3);
        row[op] = hp; row[DD / 2 + op] = lp; row[DD + op] = hp;     // (hi, lo, hi)
    }
    if (idx < DD * (KB5 / 2)) {
        int d = idx / (KB5 / 2), fp = idx % (KB5 / 2);
        float v0 = 0.0f, v1 = 0.0f;
        if (fp < FF) {
            int f = fp;
            bool edge = (f == 0) || (f == DD / 2);
            float c = edge ? (1.0f / DD) : (2.0f / DD);
            int r = (f * d) % DD;
            float ang = w * (float)r;
            v0 = c * cosf(ang);
            v1 = edge ? 0.0f : -c * sinf(ang);
        }
        uint32_t* row = (uint32_t*)(d_ITb + (size_t)d * KB5);
        row[fp] = packh(__float2half(v0), __float2half(v1));
    }
}

// ---------------- W^T split (fold B, bf16 3-term) ----------------
__global__ void splitW_kernel(const float* __restrict__ Wk, const float* __restrict__ Wv,
                              const float* __restrict__ Wq) {
    int idx = blockIdx.x * blockDim.x + threadIdx.x;
    if (idx >= 3 * (DD / 2) * DD) return;
    int z = idx / ((DD / 2) * DD);
    int rem = idx % ((DD / 2) * DD);
    int op = rem / DD, in = rem % DD;
    const float* W = (z == 0) ? Wk : (z == 1) ? Wv : Wq;
    float v0 = W[(size_t)(2 * op) * DD + in];
    float v1 = W[(size_t)(2 * op + 1) * DD + in];
    uint32_t lp, hp = packsplit_b(v0, v1, lp);
    uint32_t* row = (uint32_t*)(d_Ws + (size_t)(z * DD + in) * K3);
    row[op] = hp; row[DD / 2 + op] = hp; row[DD + op] = lp;         // (hi, hi, lo)
}

// ---------------- X convert (stage-3 B, fp16 hi only) ----------------
__global__ void split_X_kernel(const float* __restrict__ x) {
    int idx = blockIdx.x * blockDim.x + threadIdx.x;
    if (idx >= RR * DD / 2) return;
    int r = idx / (DD / 2), cp = idx % (DD / 2);
    float2 v = *(const float2*)&x[(size_t)r * DD + cp * 2];
    ((uint32_t*)(d_Xs + (size_t)r * KB3))[cp] = packh(__float2half(v.x), __float2half(v.y));
}

// ---------------- HMMA GEMM: C[m,n] = sum_k A[m,k]*B[n,k] ----------------
// CTA tile 128xNT, 8 warps (2m x 4n), warp tile 64x(NT/4), BK=64.
// 4-stage cp.async pipeline, single barrier per chunk, 3-deep prefetch.
// MODE 0: fp32 C.  MODE 1: C = resid + gain[0]*4096*acc.
// MODE 2 (fold, bf16): fp16-split store into d_Gs (+z slot), masked col<SLOT.
#define WG(n) asm volatile("cp.async.wait_group " #n ";" ::: "memory")
template <int MODE, int NT>
__global__ __launch_bounds__(256, 1) void hmma_gemm(
    int NKT, int BPER,
    const __nv_bfloat16* __restrict__ A, int lda,
    const __nv_bfloat16* __restrict__ B, int ldb,
    float* __restrict__ C, int ldc,
    const float* __restrict__ resid, const float* __restrict__ gain)
{
    constexpr int NFR = NT / 32;                 // n-frags per warp
    constexpr uint32_t ASZ = 16384u;
    constexpr uint32_t BSZ = (uint32_t)NT * 128u;
    constexpr uint32_t STG = ASZ + BSZ;

    extern __shared__ char smraw[];
    const uint32_t sbase = (s2u(smraw) + 1023u) & ~1023u;
    const int t = threadIdx.x;
    const int lane = t & 31, w = t >> 5;
    const int wm = w >> 2, wn = w & 3;
    const int m0 = blockIdx.x * 128, n0 = blockIdx.y * NT;
    if (MODE == 2) B += (size_t)blockIdx.z * DD * ldb;

    float acc[4][NFR][4];
#pragma unroll
    for (int i = 0; i < 4; i++)
#pragma unroll
        for (int j = 0; j < NFR; j++)
#pragma unroll
            for (int q = 0; q < 4; q++) acc[i][j][q] = 0.0f;

    const int arow = wm * 64 + (lane & 15);
    const int akoff = (lane >> 4) * 16;
    const int brow0 = (lane & 7) + ((lane >> 4) * 8);
    const int bkoff = ((lane >> 3) & 1) * 16;

    auto issue = [&](int kt) {
        const uint32_t sA = sbase + (uint32_t)(kt & 3) * STG;
        const uint32_t sB = sA + ASZ;
        const int bkt = kt % BPER;
#pragma unroll
        for (int i = 0; i < 4; i++) {
            const int s = t + i * 256, row = s >> 3, c = s & 7;
            CP16(sA + swz((uint32_t)(row * 128 + c * 16)),
                 (const char*)A + ((size_t)(m0 + row) * lda + kt * 64 + c * 8) * 2);
        }
#pragma unroll
        for (int i = 0; i < NT / 32; i++) {
            const int s = t + i * 256, row = s >> 3, c = s & 7;
            CP16(sB + swz((uint32_t)(row * 128 + c * 16)),
                 (const char*)B + ((size_t)(n0 + row) * ldb + bkt * 64 + c * 8) * 2);
        }
        CP_COMMIT();
    };

    issue(0);
    if (NKT > 1) issue(1);
    if (NKT > 2) issue(2);
    for (int kt = 0; kt < NKT; kt++) {
        if (kt + 2 < NKT)      { WG(2); }
        else if (kt + 1 < NKT) { WG(1); }
        else                   { WG(0); }
        __syncthreads();
        if (kt + 3 < NKT) issue(kt + 3);

        const uint32_t sA = sbase + (uint32_t)(kt & 3) * STG;
        const uint32_t sB = sA + ASZ;
#pragma unroll
        for (int k16 = 0; k16 < 4; k16++) {
            uint32_t a[4][4];
#pragma unroll
            for (int mf = 0; mf < 4; mf++) {
                uint32_t addr = sA + swz((uint32_t)((arow + mf * 16) * 128 + k16 * 32 + akoff));
                asm volatile("ldmatrix.sync.aligned.m8n8.x4.shared.b16 {%0,%1,%2,%3}, [%4];"
                    : "=r"(a[mf][0]), "=r"(a[mf][1]), "=r"(a[mf][2]), "=r"(a[mf][3]) : "r"(addr));
            }
#pragma unroll
            for (int p = 0; p < NT / 64; p++) {
                uint32_t q0, q1, q2, q3;
                uint32_t addr = sB + swz((uint32_t)((wn * (NT / 4) + p * 16 + brow0) * 128 + k16 * 32 + bkoff));
                asm volatile("ldmatrix.sync.aligned.m8n8.x4.shared.b16 {%0,%1,%2,%3}, [%4];"
                    : "=r"(q0), "=r"(q1), "=r"(q2), "=r"(q3) : "r"(addr));
#pragma unroll
                for (int mf = 0; mf < 4; mf++) {
                    mma16816<MODE == 2>(acc[mf][2 * p], a[mf], q0, q1);
                    mma16816<MODE == 2>(acc[mf][2 * p + 1], a[mf], q2, q3);
                }
            }
        }
    }

    // ---------------- epilogue ----------------
    const int r = lane >> 2, c2 = (lane & 3) * 2;
    if (MODE == 2) {
        __half* gbase = d_Gs + (size_t)blockIdx.z * SLOT * KA3;
#pragma unroll
        for (int mf = 0; mf < 4; mf++) {
#pragma unroll
            for (int nf = 0; nf < NFR; nf++) {
                const int ml = m0 + wm * 64 + mf * 16 + r;
                const int n = n0 + wn * (NT / 4) + nf * 8 + c2;
#pragma unroll
                for (int hh = 0; hh < 2; hh++) {
                    const int mrow = ml + hh * 8;
                    if (mrow < SLOT) {
                        uint32_t lp, hp = packsplit_h(acc[mf][nf][2 * hh], acc[mf][nf][2 * hh + 1], lp);
                        uint32_t* orow = (uint32_t*)(gbase + (size_t)mrow * KA3);
                        orow[n / 2] = hp; orow[KB3 / 2 + n / 2] = lp;   // (hi | lo)
                    }
                }
            }
        }
        return;
    }
    const float g = (MODE == 1) ? gain[0] * ISCALE5 : 0.0f;
#pragma unroll
    for (int mf = 0; mf < 4; mf++) {
#pragma unroll
        for (int nf = 0; nf < NFR; nf++) {
            const int m = m0 + wm * 64 + mf * 16 + r;
            const int n = n0 + wn * (NT / 4) + nf * 8 + c2;
            const size_t o0 = (size_t)m * ldc + n;
            const size_t o1 = (size_t)(m + 8) * ldc + n;
            if (MODE == 1) {
                float2 x0 = *(const float2*)&resid[o0];
                float2 x1 = *(const float2*)&resid[o1];
                *(float2*)&C[o0] = make_float2(x0.x + g * acc[mf][nf][0], x0.y + g * acc[mf][nf][1]);
                *(float2*)&C[o1] = make_float2(x1.x + g * acc[mf][nf][2], x1.y + g * acc[mf][nf][3]);
            } else {
                *(float2*)&C[o0] = make_float2(acc[mf][nf][0], acc[mf][nf][1]);
                *(float2*)&C[o1] = make_float2(acc[mf][nf][2], acc[mf][nf][3]);
            }
        }
    }
}

// ---------------- causal scan (shuffle-based), fused fp16-split + 2^-12 prescale ----------------
__global__ __launch_bounds__(512) void scan_kernel() {
    const int f = blockIdx.x;
    const int b = blockIdx.y;
    const int base = b * SS;
    const int t = threadIdx.x;
    const int lane = t & 31, wid = t >> 5;
    const int s0 = t * 8;

    const float* kre = d_XFt + (size_t)(0 * SLOT + f)      * RR + base;
    const float* kim = d_XFt + (size_t)(0 * SLOT + FF + f) * RR + base;
    const float* vre = d_XFt + (size_t)(1 * SLOT + f)      * RR + base;
    const float* vim = d_XFt + (size_t)(1 * SLOT + FF + f) * RR + base;
    const float* qre = d_XFt + (size_t)(2 * SLOT + f)      * RR + base;
    const float* qim = d_XFt + (size_t)(2 * SLOT + FF + f) * RR + base;

    float kr[8], ki[8], vr[8], vi[8], qr[8], qi[8];
#pragma unroll
    for (int h = 0; h < 2; h++) {
        *(float4*)(kr + 4 * h) = *(const float4*)(kre + s0 + 4 * h);
        *(float4*)(ki + 4 * h) = *(const float4*)(kim + s0 + 4 * h);
        *(float4*)(vr + 4 * h) = *(const float4*)(vre + s0 + 4 * h);
        *(float4*)(vi + 4 * h) = *(const float4*)(vim + s0 + 4 * h);
        *(float4*)(qr + 4 * h) = *(const float4*)(qre + s0 + 4 * h);
        *(float4*)(qi + 4 * h) = *(const float4*)(qim + s0 + 4 * h);
    }

    float lr[8], li[8], runr = 0.0f, runi = 0.0f;
#pragma unroll
    for (int i = 0; i < 8; i++) {
        float zr = kr[i] * vr[i] - ki[i] * vi[i];
        float zi = kr[i] * vi[i] + ki[i] * vr[i];
        runr += zr; runi += zi;
        lr[i] = runr; li[i] = runi;
    }

    // warp inclusive scan of per-thread totals
    float wr = runr, wi = runi;
#pragma unroll
    for (int off = 1; off < 32; off <<= 1) {
        float pr = __shfl_up_sync(0xFFFFFFFFu, wr, off);
        float pi = __shfl_up_sync(0xFFFFFFFFu, wi, off);
        if (lane >= off) { wr += pr; wi += pi; }
    }
    __shared__ float swr[16], swi[16];
    if (lane == 31) { swr[wid] = wr; swi[wid] = wi; }
    __syncthreads();
    if (t < 32) {
        float vr2 = (t < 16) ? swr[t] : 0.0f;
        float vi2 = (t < 16) ? swi[t] : 0.0f;
#pragma unroll
        for (int off = 1; off < 16; off <<= 1) {
            float pr = __shfl_up_sync(0xFFFFFFFFu, vr2, off);
            float pi = __shfl_up_sync(0xFFFFFFFFu, vi2, off);
            if (lane >= off) { vr2 += pr; vi2 += pi; }
        }
        if (t < 16) { swr[t] = vr2; swi[t] = vi2; }
    }
    __syncthreads();
    const float baser = (wid > 0) ? swr[wid - 1] : 0.0f;
    const float basei = (wid > 0) ? swi[wid - 1] : 0.0f;
    const float exr = baser + (wr - runr);
    const float exi = basei + (wi - runi);

#pragma unroll
    for (int i = 0; i < 8; i++) {
        float mr = exr + lr[i];
        float mi = exi + li[i];
        float ox = (mr * qr[i] + mi * qi[i]) * SCALE5;   // Re -> j=2f
        float oy = (mi * qr[i] - mr * qi[i]) * SCALE5;   // Im -> j=2f+1
        uint32_t lp, hp = packsplit_h(ox, oy, lp);
        uint32_t* orow = (uint32_t*)(d_OFs + (size_t)(base + s0 + i) * KA5);
        orow[f] = hp; orow[KB5 / 2 + f] = lp;            // (hi | lo)
    }
}

// ---------------- launch ----------------
#define SMEM_256 (4 * (16384 + 256 * 128) + 1024)
#define SMEM_128 (4 * (16384 + 128 * 128) + 1024)
extern "C" void kernel_launch(void* const* d_in, const int* in_sizes, int n_in,
                              void* d_out, int out_size) {
    const float* x    = (const float*)d_in[0];
    const float* Wk   = (const float*)d_in[1];
    const float* Wv   = (const float*)d_in[2];
    const float* Wq   = (const float*)d_in[3];
    const float* gain = (const float*)d_in[4];
    float* out = (float*)d_out;

    void *pTwS, *pWs, *pGs, *pXs, *pOFs, *pITb, *pXFt;
    cudaGetSymbolAddress(&pTwS, d_TwS);
    cudaGetSymbolAddress(&pWs,  d_Ws);
    cudaGetSymbolAddress(&pGs,  d_Gs);
    cudaGetSymbolAddress(&pXs,  d_Xs);
    cudaGetSymbolAddress(&pOFs, d_OFs);
    cudaGetSymbolAddress(&pITb, d_ITb);
    cudaGetSymbolAddress(&pXFt, d_XFt);

    cudaFuncSetAttribute((const void*)hmma_gemm<0, 256>, cudaFuncAttributeMaxDynamicSharedMemorySize, SMEM_256);
    cudaFuncSetAttribute((const void*)hmma_gemm<1, 256>, cudaFuncAttributeMaxDynamicSharedMemorySize, SMEM_256);
    cudaFuncSetAttribute((const void*)hmma_gemm<2, 128>, cudaFuncAttributeMaxDynamicSharedMemorySize, SMEM_128);

    // 0) tables
    init_tables_kernel<<<(TWROWS * (DD / 2) + 255) / 256, 256>>>();

    // 1) W^T split (fold B) + X fp16 convert (stage-3 B)
    splitW_kernel<<<(3 * (DD / 2) * DD + 255) / 256, 256>>>(Wk, Wv, Wq);
    split_X_kernel<<<(RR * DD / 2 + 255) / 256, 256>>>(x);

    // 2) fold GEMM (bf16 3-term, NT=128 -> grid 126, fp16-split store into Gs)
    hmma_gemm<2, 128><<<dim3(TWROWS / 128, DD / 128, 3), 256, SMEM_128>>>(
        K3 / 64, K3 / 64,
        (const __nv_bfloat16*)pTwS, K3, (const __nv_bfloat16*)pWs, K3,
        nullptr, 0, nullptr, nullptr);

    // 3) stage-3 GEMM (fp16 2-term): XFt[col, r]  M=2432, N=16384, K=1536 (B period 768)
    hmma_gemm<0, 256><<<dim3(MROWS / 128, RR / 256), 256, SMEM_256>>>(
        KA3 / 64, KB3 / 64,
        (const __nv_bfloat16*)pGs, KA3, (const __nv_bfloat16*)pXs, KB3,
        (float*)pXFt, RR, nullptr, nullptr);

    // 4) causal scan -> OFs (fp16 split + prescale, fused)
    scan_kernel<<<dim3(FF, BB), 512>>>();

    // 5) stage-5 GEMM + residual (fp16 2-term): out[r,d]  M=16384, N=768, K=1664 (B period 832)
    hmma_gemm<1, 256><<<dim3(RR / 128, DD / 256), 256, SMEM_256>>>(
        KA5 / 64, KB5 / 64,
        (const __nv_bfloat16*)pOFs, KA5, (const __nv_bfloat16*)pITb, KB5,
        out, DD, x, gain);
}